// round 3
// baseline (speedup 1.0000x reference)
#include <cuda_runtime.h>

#define CC      32
#define TT      256
#define HALO    63
#define EXT     319          // TT + HALO
#define NTHR    320
#define LLEN    90000
#define NTILES  352          // ceil(90000/256)
#define NB      8
#define DOWNL   22500
#define FLATN   (64*DOWNL)   // 1,440,000
#define SLICE   3200
#define NSLICE  450          // 1,440,000 / 3200

// scratch (static device globals: no runtime allocation)
__device__ float g_y[NB * FLATN];             // downsampled feature map [8][64][22500]
__device__ float g_partial[NSLICE * 64 * NB]; // FC partial sums

// ---------------------------------------------------------------------------
// Kernel 1: fused initial conv + 6 wavenet blocks + stride-4 downsample conv.
// One CTA = one (batch, 256-position tile). h lives entirely in shared memory
// (left halo of 63 covers the cumulative receptive field of all dilations).
// ---------------------------------------------------------------------------
__global__ __launch_bounds__(NTHR, 1)
void k_wavenet(const float* __restrict__ x,
               const float* __restrict__ w0, const float* __restrict__ b0,
               const float* __restrict__ Wf, const float* __restrict__ bf,
               const float* __restrict__ Wg, const float* __restrict__ bg,
               const float* __restrict__ Ws, const float* __restrict__ bs,
               const float* __restrict__ Wr, const float* __restrict__ br,
               const float* __restrict__ wd, const float* __restrict__ bd)
{
    extern __shared__ float sm[];
    float* hs    = sm;                    // [CC][NTHR]  h tile (in-place updated)
    float* wbuf  = hs + CC*NTHR;          // 8192 floats: wfg[1024 float4] | wsrT[2048]
    float* skipb = wbuf + 8192;           // [CC][TT]    skip staging for downsample
    float* bbuf  = skipb + CC*TT;         // 128 floats: bf|bg|bs|br of current block
    float* xs    = bbuf + 128;            // EXT+2 input samples

    const int b    = blockIdx.y;
    const int tile = blockIdx.x;
    const int l0   = tile * TT;
    const int t    = threadIdx.x;
    const int p    = l0 - HALO + t;       // owned sequence position (t < EXT)

    // ---- load x tile (with 65-left halo: 63 for blocks + 2 for K=3 conv) ----
    for (int i = t; i < EXT + 2; i += NTHR) {
        int gp = l0 - HALO - 2 + i;
        xs[i] = (gp >= 0 && gp < LLEN) ? x[(size_t)b*LLEN + gp] : 0.f;
    }
    __syncthreads();

    // ---- initial causal conv K=3: h[c][t] ----
    if (t < EXT) {
        if (p >= 0 && p < LLEN) {
            float x0 = xs[t], x1 = xs[t+1], x2 = xs[t+2];
            #pragma unroll
            for (int c = 0; c < CC; c++) {
                hs[c*NTHR + t] = __ldg(&b0[c]) + __ldg(&w0[c*3+0])*x0
                               + __ldg(&w0[c*3+1])*x1 + __ldg(&w0[c*3+2])*x2;
            }
        } else {
            #pragma unroll
            for (int c = 0; c < CC; c++) hs[c*NTHR + t] = 0.f;  // causal zero-pad
        }
    }

    float skip[CC];
    #pragma unroll
    for (int c = 0; c < CC; c++) skip[c] = 0.f;
    const bool doskip = (t >= HALO) && (t < EXT) && (p < LLEN);

    // ---- 6 dilated residual blocks ----
    for (int blk = 0; blk < 6; blk++) {
        const int d = 1 << blk;

        // stage weights: wfg[o][c] = (Wf0,Wf1,Wg0,Wg1); wsrT[o][oo] = (Ws[oo][o], Wr[oo][o])
        for (int idx = t; idx < 1024; idx += NTHR) {
            float4 v;
            v.x = Wf[(blk*1024 + idx)*2 + 0];
            v.y = Wf[(blk*1024 + idx)*2 + 1];
            v.z = Wg[(blk*1024 + idx)*2 + 0];
            v.w = Wg[(blk*1024 + idx)*2 + 1];
            ((float4*)wbuf)[idx] = v;
            int oo = idx >> 5, o = idx & 31;          // global layout Ws[oo][o]
            float2 u;
            u.x = Ws[blk*1024 + idx];
            u.y = Wr[blk*1024 + idx];
            ((float2*)(wbuf + 4096))[o*CC + oo] = u;  // transposed for inner loop
        }
        if (t < 32) {
            bbuf[t]      = bf[blk*CC + t];
            bbuf[32 + t] = bg[blk*CC + t];
            bbuf[64 + t] = bs[blk*CC + t];
            bbuf[96 + t] = br[blk*CC + t];
        }
        __syncthreads();

        const int S = (2 << blk) - 1;   // first valid column for this block
        const bool act = (t >= S) && (t < EXT) && (p >= 0) && (p < LLEN);
        float racc[CC];

        if (act) {
            float hc[CC], hp[CC];
            #pragma unroll
            for (int c = 0; c < CC; c++) {
                hc[c] = hs[c*NTHR + t];
                hp[c] = hs[c*NTHR + t - d];
            }
            #pragma unroll
            for (int c = 0; c < CC; c++) racc[c] = bbuf[96 + c];
            if (doskip) {
                #pragma unroll
                for (int c = 0; c < CC; c++) skip[c] += bbuf[64 + c];
            }

            #pragma unroll 1
            for (int o = 0; o < CC; o++) {
                float af0 = bbuf[o],      af1 = 0.f;
                float ag0 = bbuf[32 + o], ag1 = 0.f;
                const float4* wp = ((const float4*)wbuf) + o*CC;
                #pragma unroll
                for (int c = 0; c < CC; c += 2) {
                    float4 wa = wp[c];
                    af0 = fmaf(wa.x, hp[c],   af0); af0 = fmaf(wa.y, hc[c],   af0);
                    ag0 = fmaf(wa.z, hp[c],   ag0); ag0 = fmaf(wa.w, hc[c],   ag0);
                    float4 wb = wp[c+1];
                    af1 = fmaf(wb.x, hp[c+1], af1); af1 = fmaf(wb.y, hc[c+1], af1);
                    ag1 = fmaf(wb.z, hp[c+1], ag1); ag1 = fmaf(wb.w, hc[c+1], ag1);
                }
                float af = af0 + af1, ag = ag0 + ag1;
                // tanh via exp (overflow-safe), sigmoid via exp; rel err ~1e-6
                float e2 = __expf(-2.f * fabsf(af));
                float th = copysignf(__fdividef(1.f - e2, 1.f + e2), af);
                float sg = __fdividef(1.f, 1.f + __expf(-ag));
                float out_o = th * sg;

                const float4* wsp = ((const float4*)(wbuf + 4096)) + o*(CC/2);
                if (doskip) {
                    #pragma unroll
                    for (int oo = 0; oo < CC; oo += 2) {
                        float4 w = wsp[oo >> 1];
                        skip[oo]   = fmaf(w.x, out_o, skip[oo]);
                        racc[oo]   = fmaf(w.y, out_o, racc[oo]);
                        skip[oo+1] = fmaf(w.z, out_o, skip[oo+1]);
                        racc[oo+1] = fmaf(w.w, out_o, racc[oo+1]);
                    }
                } else {
                    #pragma unroll
                    for (int oo = 0; oo < CC; oo += 2) {
                        float4 w = wsp[oo >> 1];
                        racc[oo]   = fmaf(w.y, out_o, racc[oo]);
                        racc[oo+1] = fmaf(w.w, out_o, racc[oo+1]);
                    }
                }
            }
        }
        __syncthreads();                       // all hs reads done
        if (act) {
            #pragma unroll
            for (int c = 0; c < CC; c++) hs[c*NTHR + t] += racc[c];   // h += r
        }
        __syncthreads();                       // hs updated for next block
    }

    // ---- stage skip to smem ----
    if (t >= HALO && t < EXT) {
        int j = t - HALO;
        #pragma unroll
        for (int c = 0; c < CC; c++) skipb[c*TT + j] = (p < LLEN) ? skip[c] : 0.f;
    }
    __syncthreads();

    // ---- downsample conv: 64 out-ch, K=4, stride 4 (reuse wbuf for wd) ----
    for (int idx = t; idx < 2048; idx += NTHR)
        ((float4*)wbuf)[idx] = ((const float4*)wd)[idx];   // 64*32*4 = 8192 floats
    __syncthreads();

    const int m0 = tile * (TT/4);
    for (int idx = t; idx < 64*64; idx += NTHR) {
        int m = idx & 63, o = idx >> 6;
        int mg = m0 + m;
        if (mg < DOWNL) {
            float acc = __ldg(&bd[o]);
            #pragma unroll
            for (int c = 0; c < CC; c++) {
                float4 w  = ((const float4*)wbuf)[o*CC + c];
                float4 s4 = ((const float4*)skipb)[c*(TT/4) + m];
                acc += w.x*s4.x + w.y*s4.y + w.z*s4.z + w.w*s4.w;
            }
            g_y[(size_t)b*FLATN + (size_t)o*DOWNL + mg] = acc;
        }
    }
}

// ---------------------------------------------------------------------------
// Kernel 2: FC partials. One CTA per 3200-element f-slice; y slice cached in
// smem, each warp handles 8 fcW rows (as 4 pairs sharing y loads).
// ---------------------------------------------------------------------------
__global__ __launch_bounds__(256)
void k_fc(const float* __restrict__ fcW)
{
    extern __shared__ float ys[];   // [NB][SLICE]
    const int t = threadIdx.x;
    const int slice = blockIdx.x;
    const size_t f0 = (size_t)slice * SLICE;

    for (int idx = t; idx < NB*(SLICE/4); idx += 256) {
        int bb = idx / (SLICE/4);
        int q  = idx % (SLICE/4);
        ((float4*)ys)[idx] = ((const float4*)(g_y + (size_t)bb*FLATN + f0))[q];
    }
    __syncthreads();

    const int warp = t >> 5, lane = t & 31;
    #pragma unroll 1
    for (int jp = 0; jp < 4; jp++) {
        int j0 = warp*8 + jp*2;
        const float4* w0p = (const float4*)(fcW + (size_t)j0*FLATN + f0);
        const float4* w1p = (const float4*)(fcW + (size_t)(j0+1)*FLATN + f0);
        float a0[NB], a1[NB];
        #pragma unroll
        for (int bb = 0; bb < NB; bb++) { a0[bb] = 0.f; a1[bb] = 0.f; }

        for (int q = lane; q < SLICE/4; q += 32) {
            float4 w0v = __ldg(w0p + q);
            float4 w1v = __ldg(w1p + q);
            #pragma unroll
            for (int bb = 0; bb < NB; bb++) {
                float4 yv = ((const float4*)ys)[bb*(SLICE/4) + q];
                a0[bb] += w0v.x*yv.x + w0v.y*yv.y + w0v.z*yv.z + w0v.w*yv.w;
                a1[bb] += w1v.x*yv.x + w1v.y*yv.y + w1v.z*yv.z + w1v.w*yv.w;
            }
        }
        #pragma unroll
        for (int bb = 0; bb < NB; bb++) {
            #pragma unroll
            for (int off = 16; off > 0; off >>= 1) {
                a0[bb] += __shfl_xor_sync(0xffffffffu, a0[bb], off);
                a1[bb] += __shfl_xor_sync(0xffffffffu, a1[bb], off);
            }
        }
        if (lane == 0) {
            #pragma unroll
            for (int bb = 0; bb < NB; bb++) {
                g_partial[((size_t)slice*64 + j0  )*NB + bb] = a0[bb];
                g_partial[((size_t)slice*64 + j0+1)*NB + bb] = a1[bb];
            }
        }
    }
}

// ---------------------------------------------------------------------------
// Kernel 3: reduce FC partials, add bias, reparameterize, write (mu,logvar,z)
// ---------------------------------------------------------------------------
__global__ void k_final(const float* __restrict__ fcb,
                        const float* __restrict__ eps,
                        float* __restrict__ out)
{
    __shared__ float os[64][NB];
    const int t = threadIdx.x;           // 512 threads
    const int j = t >> 3, bb = t & 7;
    float acc = fcb[j];
    for (int s = 0; s < NSLICE; s++)
        acc += g_partial[(size_t)s*64*NB + t];   // (s*64+j)*8+bb == s*512+t
    os[j][bb] = acc;
    __syncthreads();
    if (t < 256) {
        int b2 = t >> 5, c = t & 31;
        float mu = os[c][b2];
        float lv = os[c + 32][b2];
        float z  = mu + eps[b2*32 + c] * expf(0.5f * lv);
        out[        b2*32 + c] = mu;
        out[256  +  b2*32 + c] = lv;
        out[512  +  b2*32 + c] = z;
    }
}

// ---------------------------------------------------------------------------
extern "C" void kernel_launch(void* const* d_in, const int* in_sizes, int n_in,
                              void* d_out, int out_size)
{
    const float* x   = (const float*)d_in[0];
    const float* eps = (const float*)d_in[1];
    const float* w0  = (const float*)d_in[2];
    const float* b0  = (const float*)d_in[3];
    const float* Wf  = (const float*)d_in[4];
    const float* bf  = (const float*)d_in[5];
    const float* Wg  = (const float*)d_in[6];
    const float* bg  = (const float*)d_in[7];
    const float* Ws  = (const float*)d_in[8];
    const float* bs  = (const float*)d_in[9];
    const float* Wr  = (const float*)d_in[10];
    const float* br  = (const float*)d_in[11];
    const float* wd  = (const float*)d_in[12];
    const float* bd  = (const float*)d_in[13];
    const float* fcW = (const float*)d_in[14];
    const float* fcb = (const float*)d_in[15];
    float* out = (float*)d_out;

    const int smem1 = (CC*NTHR + 8192 + CC*TT + 128 + EXT + 2) * (int)sizeof(float);
    const int smem2 = NB * SLICE * (int)sizeof(float);
    cudaFuncSetAttribute(k_wavenet, cudaFuncAttributeMaxDynamicSharedMemorySize, smem1);
    cudaFuncSetAttribute(k_fc,      cudaFuncAttributeMaxDynamicSharedMemorySize, smem2);

    dim3 g1(NTILES, NB);
    k_wavenet<<<g1, NTHR, smem1>>>(x, w0, b0, Wf, bf, Wg, bg, Ws, bs, Wr, br, wd, bd);
    k_fc<<<NSLICE, 256, smem2>>>(fcW);
    k_final<<<1, 512>>>(fcb, eps, out);
}

// round 4
// speedup vs baseline: 2.2772x; 2.2772x over previous
#include <cuda_runtime.h>

typedef unsigned long long u64;

#define CC      32
#define TT      256
#define HALO    63
#define NTHR    320
#define LLEN    90000
#define NTILES  352
#define NB      8
#define DOWNL   22500
#define FLATN   (64*DOWNL)
#define SLICE   3200
#define NSLICE  450

#define STR     328
#define OFF_HS  64
#define OFF_OUT (OFF_HS + 32*STR)      // 10560
#define OFF_WFG (OFF_OUT + 32*STR)     // 21056
#define OFF_WSR (OFF_WFG + 4096)       // 25152
#define OFF_B   (OFF_WSR + 2048)       // 27200
#define OFF_XS  (OFF_B + 128)          // 27328
#define SMF     (OFF_XS + 324)         // 27652 floats ~108KB

__device__ float g_y[NB * FLATN];
__device__ float g_partial[NSLICE * 64 * NB];

// ---- f32x2 helpers ----
__device__ __forceinline__ u64 f2fma(u64 a, u64 b, u64 c) {
    u64 d; asm("fma.rn.f32x2 %0, %1, %2, %3;" : "=l"(d) : "l"(a), "l"(b), "l"(c)); return d;
}
__device__ __forceinline__ u64 dup2(float x) {
    u64 d; unsigned r = __float_as_uint(x);
    asm("mov.b64 %0, {%1, %1};" : "=l"(d) : "r"(r)); return d;
}
__device__ __forceinline__ float2 unp(u64 a) {
    unsigned x, y; asm("mov.b64 {%0, %1}, %2;" : "=r"(x), "=r"(y) : "l"(a));
    return make_float2(__uint_as_float(x), __uint_as_float(y));
}

// ---------------------------------------------------------------------------
// Phase A: gated conv for 4 outputs (o=og*4+i) x 8 positions (base..base+7).
// Weights staged as float4 (f0,g0,f1,g1) at [c][i][og] -> conflict-free LDS.
// acc pair = (f_acc, g_acc).
// ---------------------------------------------------------------------------
template<int D>
__device__ __forceinline__ void phaseA(float* sm, int og, int base)
{
    u64 acc[4][8];
    #pragma unroll
    for (int i = 0; i < 4; i++) {
        u64 bv = *(const u64*)(sm + OFF_B + 2*(og*4 + i));
        #pragma unroll
        for (int j = 0; j < 8; j++) acc[i][j] = bv;
    }
    const ulonglong2* wv = (const ulonglong2*)(sm + OFF_WFG);
    const float* hb = sm + OFF_HS + base;

    #pragma unroll 2
    for (int c = 0; c < 32; c++) {
        const float* hr = hb + c*STR;
        float4 hc0 = *(const float4*)(hr);
        float4 hc1 = *(const float4*)(hr + 4);
        float hcv[8] = {hc0.x,hc0.y,hc0.z,hc0.w,hc1.x,hc1.y,hc1.z,hc1.w};
        float hp[8];
        if (D < 8) {
            float4 vp = *(const float4*)(hr - 4);
            float tmp[12] = {vp.x,vp.y,vp.z,vp.w,
                             hc0.x,hc0.y,hc0.z,hc0.w,
                             hc1.x,hc1.y,hc1.z,hc1.w};
            #pragma unroll
            for (int j = 0; j < 8; j++) hp[j] = tmp[4 - D + j];
        } else {
            float4 a0 = *(const float4*)(hr - D);
            float4 a1 = *(const float4*)(hr - D + 4);
            hp[0]=a0.x; hp[1]=a0.y; hp[2]=a0.z; hp[3]=a0.w;
            hp[4]=a1.x; hp[5]=a1.y; hp[6]=a1.z; hp[7]=a1.w;
        }
        ulonglong2 w[4];
        #pragma unroll
        for (int i = 0; i < 4; i++) w[i] = wv[c*32 + i*8 + og];
        #pragma unroll
        for (int j = 0; j < 8; j++) {
            u64 hpd = dup2(hp[j]), hcd = dup2(hcv[j]);
            #pragma unroll
            for (int i = 0; i < 4; i++) {
                acc[i][j] = f2fma(w[i].x, hpd, acc[i][j]);   // (f,g) += (Wf0,Wg0)*h[t-d]
                acc[i][j] = f2fma(w[i].y, hcd, acc[i][j]);   // (f,g) += (Wf1,Wg1)*h[t]
            }
        }
    }
    // activation + store out
    #pragma unroll
    for (int i = 0; i < 4; i++) {
        float ov[8];
        #pragma unroll
        for (int j = 0; j < 8; j++) {
            float2 fg = unp(acc[i][j]);
            float e2 = __expf(-2.f * fabsf(fg.x));
            float th = copysignf(__fdividef(1.f - e2, 1.f + e2), fg.x);
            float sg = __fdividef(1.f, 1.f + __expf(-fg.y));
            ov[j] = th * sg;
        }
        float* op = sm + OFF_OUT + (og*4 + i)*STR + base;
        *(float4*)op     = make_float4(ov[0], ov[1], ov[2], ov[3]);
        *(float4*)(op+4) = make_float4(ov[4], ov[5], ov[6], ov[7]);
    }
}

// ---------------------------------------------------------------------------
// Phase B: s/r GEMM for 4 outputs (oo=oog*4+i) x 8 positions. acc pair=(s,r).
// skip kept in caller registers (sacc); h updated in-place in smem.
// ---------------------------------------------------------------------------
__device__ __forceinline__ void phaseB(float* sm, int oog, int base,
                                       float sacc[4][8], bool edge)
{
    u64 acc[4][8];
    #pragma unroll
    for (int i = 0; i < 4; i++) {
        u64 bv = *(const u64*)(sm + OFF_B + 64 + 2*(oog*4 + i));
        #pragma unroll
        for (int j = 0; j < 8; j++) acc[i][j] = bv;
    }
    const ulonglong2* wv = (const ulonglong2*)(sm + OFF_WSR);
    const float* ob = sm + OFF_OUT + base;

    #pragma unroll 2
    for (int o = 0; o < 32; o++) {
        ulonglong2 w01 = wv[o*16 + oog];
        ulonglong2 w23 = wv[o*16 + 8 + oog];
        float4 v0 = *(const float4*)(ob + o*STR);
        float4 v1 = *(const float4*)(ob + o*STR + 4);
        float ov[8] = {v0.x,v0.y,v0.z,v0.w,v1.x,v1.y,v1.z,v1.w};
        #pragma unroll
        for (int j = 0; j < 8; j++) {
            u64 od = dup2(ov[j]);
            acc[0][j] = f2fma(w01.x, od, acc[0][j]);
            acc[1][j] = f2fma(w01.y, od, acc[1][j]);
            acc[2][j] = f2fma(w23.x, od, acc[2][j]);
            acc[3][j] = f2fma(w23.y, od, acc[3][j]);
        }
    }
    // epilogue: sacc += s ; h += r (mask p<0 on tile 0)
    #pragma unroll
    for (int i = 0; i < 4; i++) {
        float* hp_ = sm + OFF_HS + (oog*4 + i)*STR + base;
        float4 h0 = *(float4*)hp_, h1 = *(float4*)(hp_ + 4);
        float hv[8] = {h0.x,h0.y,h0.z,h0.w,h1.x,h1.y,h1.z,h1.w};
        #pragma unroll
        for (int j = 0; j < 8; j++) {
            float2 sr = unp(acc[i][j]);
            sacc[i][j] += sr.x;
            float r = sr.y;
            if (edge && (base + j < HALO)) r = 0.f;   // keep h=0 for p<0
            hv[j] += r;
        }
        *(float4*)hp_     = make_float4(hv[0], hv[1], hv[2], hv[3]);
        *(float4*)(hp_+4) = make_float4(hv[4], hv[5], hv[6], hv[7]);
    }
}

// ---------------------------------------------------------------------------
__global__ __launch_bounds__(NTHR, 1)
void k_wavenet(const float* __restrict__ x,
               const float* __restrict__ w0, const float* __restrict__ b0,
               const float* __restrict__ Wf, const float* __restrict__ bf,
               const float* __restrict__ Wg, const float* __restrict__ bg,
               const float* __restrict__ Ws, const float* __restrict__ bs,
               const float* __restrict__ Wr, const float* __restrict__ br,
               const float* __restrict__ wd, const float* __restrict__ bd)
{
    extern __shared__ float sm[];
    const int b = blockIdx.y, tile = blockIdx.x, t = threadIdx.x;
    const int l0 = tile * TT;

    // stage x (positions l0-65 .. l0+258)
    for (int i = t; i < 324; i += NTHR) {
        int gp = l0 - 65 + i;
        sm[OFF_XS + i] = (gp >= 0 && gp < LLEN) ? x[(size_t)b*LLEN + gp] : 0.f;
    }
    if (t < 64) sm[t] = 0.f;   // zero pad before hs
    __syncthreads();

    // initial causal conv K=3 -> hs[c][t], t = 0..319 (pos), p = l0-63+t
    {
        float x0 = sm[OFF_XS + t], x1 = sm[OFF_XS + t + 1], x2 = sm[OFF_XS + t + 2];
        int p = l0 - HALO + t;
        bool v = (p >= 0 && p < LLEN);
        #pragma unroll
        for (int c = 0; c < CC; c++) {
            float h = v ? (__ldg(&b0[c]) + __ldg(&w0[3*c])*x0
                           + __ldg(&w0[3*c+1])*x1 + __ldg(&w0[3*c+2])*x2) : 0.f;
            sm[OFF_HS + c*STR + t] = h;
        }
    }

    const int og = t & 7, base = (t >> 3) * 8;
    const bool edge = (l0 == 0) && (base < 64);
    float sacc[4][8];
    #pragma unroll
    for (int i = 0; i < 4; i++)
        #pragma unroll
        for (int j = 0; j < 8; j++) sacc[i][j] = 0.f;

    for (int blk = 0; blk < 6; blk++) {
        __syncthreads();
        // stage weights for this block
        for (int idx = t; idx < 1024; idx += NTHR) {
            int o = idx & 31, c = idx >> 5;
            int wi = (c*32 + (o & 3)*8 + (o >> 2)) * 4;
            const float* wfp = Wf + ((size_t)(blk*32 + o)*32 + c) * 2;
            const float* wgp = Wg + ((size_t)(blk*32 + o)*32 + c) * 2;
            sm[OFF_WFG + wi + 0] = wfp[0];
            sm[OFF_WFG + wi + 1] = wgp[0];
            sm[OFF_WFG + wi + 2] = wfp[1];
            sm[OFF_WFG + wi + 3] = wgp[1];
            int oo = idx & 31, o2 = idx >> 5;  // Ws[blk][oo][o2]
            int ui = (o2*32 + (oo & 2)*8 + ((oo >> 2) & 7)*2 + (oo & 1)) * 2;
            sm[OFF_WSR + ui + 0] = Ws[blk*1024 + oo*32 + o2];
            sm[OFF_WSR + ui + 1] = Wr[blk*1024 + oo*32 + o2];
        }
        if (t < 32) {
            sm[OFF_B + 2*t]      = bf[blk*CC + t];
            sm[OFF_B + 2*t + 1]  = bg[blk*CC + t];
            sm[OFF_B + 64 + 2*t] = bs[blk*CC + t];
            sm[OFF_B + 65 + 2*t] = br[blk*CC + t];
        }
        __syncthreads();
        switch (blk) {
            case 0: phaseA<1>(sm, og, base);  break;
            case 1: phaseA<2>(sm, og, base);  break;
            case 2: phaseA<4>(sm, og, base);  break;
            case 3: phaseA<8>(sm, og, base);  break;
            case 4: phaseA<16>(sm, og, base); break;
            default: phaseA<32>(sm, og, base); break;
        }
        __syncthreads();
        phaseB(sm, og, base, sacc, edge);
    }
    __syncthreads();

    // dump skip registers to the out buffer
    #pragma unroll
    for (int i = 0; i < 4; i++) {
        float* p_ = sm + OFF_OUT + (og*4 + i)*STR + base;
        *(float4*)p_     = make_float4(sacc[i][0], sacc[i][1], sacc[i][2], sacc[i][3]);
        *(float4*)(p_+4) = make_float4(sacc[i][4], sacc[i][5], sacc[i][6], sacc[i][7]);
    }
    __syncthreads();

    // repack skip into [c][m] float4 (taps 63+4m..63+4m+3) in hs region
    for (int idx = t; idx < 2048; idx += NTHR) {
        int c = idx >> 6, m = idx & 63;
        const float* sp = sm + OFF_OUT + c*STR + HALO + 4*m;
        ((float4*)(sm + OFF_HS))[idx] = make_float4(sp[0], sp[1], sp[2], sp[3]);
    }
    __syncthreads();
    // stage wd into out region
    for (int idx = t; idx < 2048; idx += NTHR)
        ((float4*)(sm + OFF_OUT))[idx] = ((const float4*)wd)[idx];
    __syncthreads();

    // downsample conv: 64 out-ch, K=4, stride 4
    {
        int m = t & 63, oq0 = t >> 6;       // 5 oq slots x 64 m
        int mg = tile*64 + m;
        const float4* sdv = (const float4*)(sm + OFF_HS);
        const float4* wdv = (const float4*)(sm + OFF_OUT);
        if (mg < DOWNL) {
            for (int oq = oq0; oq < 16; oq += 5) {
                int o0 = oq * 4;
                float a0 = 0.f, a1 = 0.f, a2 = 0.f, a3 = 0.f;
                #pragma unroll 4
                for (int c = 0; c < 32; c++) {
                    float4 sv = sdv[c*64 + m];
                    float4 w_;
                    w_ = wdv[(o0+0)*32 + c]; a0 += w_.x*sv.x + w_.y*sv.y + w_.z*sv.z + w_.w*sv.w;
                    w_ = wdv[(o0+1)*32 + c]; a1 += w_.x*sv.x + w_.y*sv.y + w_.z*sv.z + w_.w*sv.w;
                    w_ = wdv[(o0+2)*32 + c]; a2 += w_.x*sv.x + w_.y*sv.y + w_.z*sv.z + w_.w*sv.w;
                    w_ = wdv[(o0+3)*32 + c]; a3 += w_.x*sv.x + w_.y*sv.y + w_.z*sv.z + w_.w*sv.w;
                }
                size_t gb = (size_t)b*FLATN + (size_t)mg;
                g_y[gb + (size_t)(o0+0)*DOWNL] = a0 + __ldg(&bd[o0+0]);
                g_y[gb + (size_t)(o0+1)*DOWNL] = a1 + __ldg(&bd[o0+1]);
                g_y[gb + (size_t)(o0+2)*DOWNL] = a2 + __ldg(&bd[o0+2]);
                g_y[gb + (size_t)(o0+3)*DOWNL] = a3 + __ldg(&bd[o0+3]);
            }
        }
    }
}

// ---------------------------------------------------------------------------
// Kernel 2: FC partials (unchanged from passing version)
// ---------------------------------------------------------------------------
__global__ __launch_bounds__(256)
void k_fc(const float* __restrict__ fcW)
{
    extern __shared__ float ys[];
    const int t = threadIdx.x;
    const int slice = blockIdx.x;
    const size_t f0 = (size_t)slice * SLICE;

    for (int idx = t; idx < NB*(SLICE/4); idx += 256) {
        int bb = idx / (SLICE/4);
        int q  = idx % (SLICE/4);
        ((float4*)ys)[idx] = ((const float4*)(g_y + (size_t)bb*FLATN + f0))[q];
    }
    __syncthreads();

    const int warp = t >> 5, lane = t & 31;
    #pragma unroll 1
    for (int jp = 0; jp < 4; jp++) {
        int j0 = warp*8 + jp*2;
        const float4* w0p = (const float4*)(fcW + (size_t)j0*FLATN + f0);
        const float4* w1p = (const float4*)(fcW + (size_t)(j0+1)*FLATN + f0);
        float a0[NB], a1[NB];
        #pragma unroll
        for (int bb = 0; bb < NB; bb++) { a0[bb] = 0.f; a1[bb] = 0.f; }

        for (int q = lane; q < SLICE/4; q += 32) {
            float4 w0v = __ldg(w0p + q);
            float4 w1v = __ldg(w1p + q);
            #pragma unroll
            for (int bb = 0; bb < NB; bb++) {
                float4 yv = ((const float4*)ys)[bb*(SLICE/4) + q];
                a0[bb] += w0v.x*yv.x + w0v.y*yv.y + w0v.z*yv.z + w0v.w*yv.w;
                a1[bb] += w1v.x*yv.x + w1v.y*yv.y + w1v.z*yv.z + w1v.w*yv.w;
            }
        }
        #pragma unroll
        for (int bb = 0; bb < NB; bb++) {
            #pragma unroll
            for (int off = 16; off > 0; off >>= 1) {
                a0[bb] += __shfl_xor_sync(0xffffffffu, a0[bb], off);
                a1[bb] += __shfl_xor_sync(0xffffffffu, a1[bb], off);
            }
        }
        if (lane == 0) {
            #pragma unroll
            for (int bb = 0; bb < NB; bb++) {
                g_partial[((size_t)slice*64 + j0  )*NB + bb] = a0[bb];
                g_partial[((size_t)slice*64 + j0+1)*NB + bb] = a1[bb];
            }
        }
    }
}

// ---------------------------------------------------------------------------
// Kernel 3: final reduce + reparameterize
// ---------------------------------------------------------------------------
__global__ void k_final(const float* __restrict__ fcb,
                        const float* __restrict__ eps,
                        float* __restrict__ out)
{
    __shared__ float os[64][NB];
    const int t = threadIdx.x;   // 512
    const int j = t >> 3, bb = t & 7;
    float acc = fcb[j];
    for (int s = 0; s < NSLICE; s++)
        acc += g_partial[(size_t)s*64*NB + t];
    os[j][bb] = acc;
    __syncthreads();
    if (t < 256) {
        int b2 = t >> 5, c = t & 31;
        float mu = os[c][b2];
        float lv = os[c + 32][b2];
        float z  = mu + eps[b2*32 + c] * expf(0.5f * lv);
        out[        b2*32 + c] = mu;
        out[256  +  b2*32 + c] = lv;
        out[512  +  b2*32 + c] = z;
    }
}

// ---------------------------------------------------------------------------
extern "C" void kernel_launch(void* const* d_in, const int* in_sizes, int n_in,
                              void* d_out, int out_size)
{
    const float* x   = (const float*)d_in[0];
    const float* eps = (const float*)d_in[1];
    const float* w0  = (const float*)d_in[2];
    const float* b0  = (const float*)d_in[3];
    const float* Wf  = (const float*)d_in[4];
    const float* bf  = (const float*)d_in[5];
    const float* Wg  = (const float*)d_in[6];
    const float* bg  = (const float*)d_in[7];
    const float* Ws  = (const float*)d_in[8];
    const float* bs  = (const float*)d_in[9];
    const float* Wr  = (const float*)d_in[10];
    const float* br  = (const float*)d_in[11];
    const float* wd  = (const float*)d_in[12];
    const float* bd  = (const float*)d_in[13];
    const float* fcW = (const float*)d_in[14];
    const float* fcb = (const float*)d_in[15];
    float* out = (float*)d_out;

    const int smem1 = SMF * (int)sizeof(float);
    const int smem2 = NB * SLICE * (int)sizeof(float);
    cudaFuncSetAttribute(k_wavenet, cudaFuncAttributeMaxDynamicSharedMemorySize, smem1);
    cudaFuncSetAttribute(k_fc,      cudaFuncAttributeMaxDynamicSharedMemorySize, smem2);

    dim3 g1(NTILES, NB);
    k_wavenet<<<g1, NTHR, smem1>>>(x, w0, b0, Wf, bf, Wg, bg, Ws, bs, Wr, br, wd, bd);
    k_fc<<<NSLICE, 256, smem2>>>(fcW);
    k_final<<<1, 512>>>(fcb, eps, out);
}